// round 1
// baseline (speedup 1.0000x reference)
#include <cuda_runtime.h>

#define B_TOT 32768
#define T_LEN 50
#define HID   32
#define NROW  128   // 4*H gate rows
#define ROWF  36    // floats per extended row: 32 Whh + 2 Wih + bias + pad
#define ROWU  18    // ull (f32 pairs) per row

typedef unsigned long long ull;

// ---- packed f32x2 helpers (sm_100+ PTX) ----
__device__ __forceinline__ ull fma2(ull a, ull b, ull c) {
    ull d; asm("fma.rn.f32x2 %0,%1,%2,%3;" : "=l"(d) : "l"(a), "l"(b), "l"(c)); return d;
}
__device__ __forceinline__ ull add2(ull a, ull b) {
    ull d; asm("add.rn.f32x2 %0,%1,%2;" : "=l"(d) : "l"(a), "l"(b)); return d;
}
__device__ __forceinline__ ull pack2(float lo, float hi) {
    ull d; asm("mov.b64 %0,{%1,%2};" : "=l"(d) : "f"(lo), "f"(hi)); return d;
}
__device__ __forceinline__ float lo2(ull v) {
    float f; asm("{ .reg .b32 t; mov.b64 {%0, t}, %1; }" : "=f"(f) : "l"(v)); return f;
}
__device__ __forceinline__ float hi2(ull v) {
    float f; asm("{ .reg .b32 t; mov.b64 {t, %0}, %1; }" : "=f"(f) : "l"(v)); return f;
}

// ---- fast activations (MUFU, ~1e-7 rel err) ----
__device__ __forceinline__ float ex2f(float x) {
    float r; asm("ex2.approx.f32 %0,%1;" : "=f"(r) : "f"(x)); return r;
}
__device__ __forceinline__ float rcpf(float x) {
    float r; asm("rcp.approx.f32 %0,%1;" : "=f"(r) : "f"(x)); return r;
}
__device__ __forceinline__ float sigm(float x) {
    return rcpf(1.0f + ex2f(-1.4426950408889634f * x));
}
__device__ __forceinline__ float tanhx(float x) {
    return fmaf(2.0f, rcpf(1.0f + ex2f(-2.8853900817779268f * x)), -1.0f);
}

// dot(row[36], hext[36]) with packed dual-FMA; row is 16B-aligned in smem.
__device__ __forceinline__ float reduce_row(const ull* __restrict__ rowp,
                                            const ull* __restrict__ h2) {
    ull a0 = 0ull, a1 = 0ull;  // (0.f,0.f) pairs
    const ulonglong2* r = reinterpret_cast<const ulonglong2*>(rowp);
#pragma unroll
    for (int q = 0; q < 9; q++) {
        ulonglong2 w = r[q];              // LDS.128 broadcast
        a0 = fma2(w.x, h2[2 * q + 0], a0);
        a1 = fma2(w.y, h2[2 * q + 1], a1);
    }
    ull s = add2(a0, a1);
    return lo2(s) + hi2(s);
}

__global__ void __launch_bounds__(32, 1) lsnn_kernel(
    const float* __restrict__ x,     // [B, T, 2]
    const float* __restrict__ W_ih,  // [128, 2]
    const float* __restrict__ W_hh,  // [128, 32]
    const float* __restrict__ b_ih,  // [128]
    const float* __restrict__ b_hh,  // [128]
    const float* __restrict__ W_out, // [1, 32]
    const float* __restrict__ b_out, // [1]
    const float* __restrict__ h0,    // [B, 32]
    const float* __restrict__ c0,    // [B, 32]
    float* __restrict__ out)         // [B, 50, 1]
{
    __shared__ __align__(16) float sw[NROW * ROWF];  // 18432 B
    __shared__ float swout[HID];
    __shared__ float sbout;

    const int tid = threadIdx.x;

    // ---- build extended weight rows in smem ----
    // W_hh part: 128 rows x 8 float4
    for (int idx = tid; idx < NROW * 8; idx += 32) {
        int k = idx >> 3, q = idx & 7;
        reinterpret_cast<float4*>(&sw[k * ROWF])[q] =
            reinterpret_cast<const float4*>(W_hh)[idx];
    }
    // tail: Wih0, Wih1, bias sum, pad
    for (int k = tid; k < NROW; k += 32) {
        sw[k * ROWF + 32] = W_ih[k * 2 + 0];
        sw[k * ROWF + 33] = W_ih[k * 2 + 1];
        sw[k * ROWF + 34] = b_ih[k] + b_hh[k];
        sw[k * ROWF + 35] = 0.0f;
    }
    if (tid < HID) swout[tid] = W_out[tid];
    if (tid == 0)  sbout = b_out[0];
    __syncthreads();

    const int b = blockIdx.x * 32 + tid;
    if (b >= B_TOT) return;

    // ---- per-batch state in registers ----
    ull   h2[18];
    float c[HID];
    float hb[HID];

    const float* h0p = h0 + (long)b * HID;
    const float* c0p = c0 + (long)b * HID;
#pragma unroll
    for (int p = 0; p < 16; p++) {
        float2 v = *reinterpret_cast<const float2*>(h0p + 2 * p);
        h2[p] = pack2(v.x, v.y);
    }
#pragma unroll
    for (int q = 0; q < 8; q++) {
        float4 v = reinterpret_cast<const float4*>(c0p)[q];
        c[4 * q + 0] = v.x; c[4 * q + 1] = v.y;
        c[4 * q + 2] = v.z; c[4 * q + 3] = v.w;
    }
    h2[17] = pack2(1.0f, 0.0f);  // bias lane

    const float* xp = x + (long)b * (T_LEN * 2);
    float2 xv = *reinterpret_cast<const float2*>(xp);
    const float bo = sbout;
    const ull* swu = reinterpret_cast<const ull*>(sw);
    float* outp = out + (long)b * T_LEN;

    for (int t = 0; t < T_LEN; t++) {
        h2[16] = pack2(xv.x, xv.y);
        float2 xn = xv;
        if (t + 1 < T_LEN) xn = *reinterpret_cast<const float2*>(xp + (t + 1) * 2);

        float oacc = 0.0f;
#pragma unroll
        for (int u = 0; u < HID; u++) {
            float gi = reduce_row(swu + (u          ) * ROWU, h2);
            float gf = reduce_row(swu + (u + 1 * HID) * ROWU, h2);
            float gg = reduce_row(swu + (u + 2 * HID) * ROWU, h2);
            float go = reduce_row(swu + (u + 3 * HID) * ROWU, h2);

            float iv = sigm(gi);
            float fv = sigm(gf);
            float gv = tanhx(gg);
            float ov = sigm(go);

            float cn = fmaf(fv, c[u], iv * gv);
            c[u] = cn;
            float hn = ov * tanhx(cn);
            hb[u] = hn;
            oacc = fmaf(hn, swout[u], oacc);
        }
#pragma unroll
        for (int p = 0; p < 16; p++) h2[p] = pack2(hb[2 * p], hb[2 * p + 1]);

        outp[t] = oacc + bo;
        xv = xn;
    }
}

extern "C" void kernel_launch(void* const* d_in, const int* in_sizes, int n_in,
                              void* d_out, int out_size) {
    const float* x     = (const float*)d_in[0];
    const float* W_ih  = (const float*)d_in[1];
    const float* W_hh  = (const float*)d_in[2];
    const float* b_ih  = (const float*)d_in[3];
    const float* b_hh  = (const float*)d_in[4];
    const float* W_out = (const float*)d_in[5];
    const float* b_out = (const float*)d_in[6];
    const float* h0    = (const float*)d_in[7];
    const float* c0    = (const float*)d_in[8];
    float* out = (float*)d_out;

    lsnn_kernel<<<B_TOT / 32, 32>>>(x, W_ih, W_hh, b_ih, b_hh,
                                    W_out, b_out, h0, c0, out);
}

// round 2
// speedup vs baseline: 1.5223x; 1.5223x over previous
#include <cuda_runtime.h>

#define T_LEN 50
// per-copy: 32 rows x 36 floats = 1152, +8 pad floats -> bank phase shifts by 8 per copy
#define CSTR 1160

typedef unsigned long long ull;

// ---- packed f32x2 helpers ----
__device__ __forceinline__ ull fma2(ull a, ull b, ull c) {
    ull d; asm("fma.rn.f32x2 %0,%1,%2,%3;" : "=l"(d) : "l"(a), "l"(b), "l"(c)); return d;
}
__device__ __forceinline__ ull add2(ull a, ull b) {
    ull d; asm("add.rn.f32x2 %0,%1,%2;" : "=l"(d) : "l"(a), "l"(b)); return d;
}
__device__ __forceinline__ ull pack2(float lo, float hi) {
    ull d; asm("mov.b64 %0,{%1,%2};" : "=l"(d) : "f"(lo), "f"(hi)); return d;
}
__device__ __forceinline__ float lo2(ull v) {
    float f; asm("{ .reg .b32 t; mov.b64 {%0, t}, %1; }" : "=f"(f) : "l"(v)); return f;
}
__device__ __forceinline__ float hi2(ull v) {
    float f; asm("{ .reg .b32 t; mov.b64 {t, %0}, %1; }" : "=f"(f) : "l"(v)); return f;
}

// ---- fast activations (MUFU, ~1e-7 rel err) ----
__device__ __forceinline__ float ex2f(float x) {
    float r; asm("ex2.approx.f32 %0,%1;" : "=f"(r) : "f"(x)); return r;
}
__device__ __forceinline__ float rcpf(float x) {
    float r; asm("rcp.approx.f32 %0,%1;" : "=f"(r) : "f"(x)); return r;
}
__device__ __forceinline__ float sigm(float x) {
    return rcpf(1.0f + ex2f(-1.4426950408889634f * x));
}
__device__ __forceinline__ float tanhx(float x) {
    return fmaf(2.0f, rcpf(1.0f + ex2f(-2.8853900817779268f * x)), -1.0f);
}

// Layout: warp = 32 lanes; lane = g*8+s. Group g handles hidden units [8g,8g+8),
// all 4 gates, for batches b0 = warp*16+s and b1 = b0+8. Two batches per thread
// amortize each weight LDS.128 over 4 FMA2.
__global__ void __launch_bounds__(64, 7) lsnn_kernel(
    const float* __restrict__ x,     // [B, T, 2]
    const float* __restrict__ W_ih,  // [128, 2]
    const float* __restrict__ W_hh,  // [128, 32]
    const float* __restrict__ b_ih,  // [128]
    const float* __restrict__ b_hh,  // [128]
    const float* __restrict__ W_out, // [1, 32]
    const float* __restrict__ b_out, // [1]
    const float* __restrict__ h0,    // [B, 32]
    const float* __restrict__ c0,    // [B, 32]
    float* __restrict__ out)         // [B, 50, 1]
{
    __shared__ __align__(16) float sw[4 * CSTR];
    __shared__ float swout[32];

    const int tid = threadIdx.x;

    // ---- stage 4 bank-phase-offset weight copies ----
    // copy g: rows r = j*4+e (j=unit-local 0..7, e=gate i,f,g,o), 36 floats each:
    //   [0:32) W_hh row, [32]=Wih0, [33]=Wih1, [34]=b_ih+b_hh, [35]=0
    for (int idx = tid; idx < 4 * 32 * 36; idx += 64) {
        int g = idx / 1152, rem = idx % 1152;
        int r = rem / 36, k = rem % 36;
        int grow = (r & 3) * 32 + g * 8 + (r >> 2);  // gate*32 + unit
        float v;
        if (k < 32)       v = W_hh[grow * 32 + k];
        else if (k == 32) v = W_ih[grow * 2 + 0];
        else if (k == 33) v = W_ih[grow * 2 + 1];
        else if (k == 34) v = b_ih[grow] + b_hh[grow];
        else              v = 0.0f;
        sw[g * CSTR + r * 36 + k] = v;
    }
    if (tid < 32) swout[tid] = W_out[tid];
    __syncthreads();

    const int lane = tid & 31;
    const int g = lane >> 3;
    const int s = lane & 7;
    const int warp = blockIdx.x * 2 + (tid >> 5);
    const int b0 = warp * 16 + s;
    const int b1 = b0 + 8;

    const float* swc = sw + g * CSTR;

    // ---- state: h packed pairs + c for own 8 units, 2 batches ----
    ull ha[16], hb[16];
    float ca[8], cb[8];
    {
        const float2* p0 = (const float2*)(h0 + (long)b0 * 32);
        const float2* p1 = (const float2*)(h0 + (long)b1 * 32);
#pragma unroll
        for (int p = 0; p < 16; p++) {
            float2 a = p0[p], b = p1[p];
            ha[p] = pack2(a.x, a.y);
            hb[p] = pack2(b.x, b.y);
        }
#pragma unroll
        for (int j = 0; j < 8; j++) {
            ca[j] = c0[(long)b0 * 32 + g * 8 + j];
            cb[j] = c0[(long)b1 * 32 + g * 8 + j];
        }
    }

    const float bo = b_out[0];
    const float* xp0 = x + (long)b0 * (T_LEN * 2);
    const float* xp1 = x + (long)b1 * (T_LEN * 2);
    float* op0 = out + (long)b0 * T_LEN;
    float* op1 = out + (long)b1 * T_LEN;

    float2 xva = *(const float2*)xp0;
    float2 xvb = *(const float2*)xp1;

    for (int t = 0; t < T_LEN; t++) {
        ull xa = pack2(xva.x, xva.y);
        ull xb = pack2(xvb.x, xvb.y);
        if (t + 1 < T_LEN) {
            xva = *(const float2*)(xp0 + 2 * (t + 1));
            xvb = *(const float2*)(xp1 + 2 * (t + 1));
        }

        float hna[8], hnb[8];
        float oa = 0.0f, ob = 0.0f;

#pragma unroll
        for (int j = 0; j < 8; j++) {
            float gate_a[4], gate_b[4];
#pragma unroll
            for (int e = 0; e < 4; e++) {
                const ulonglong2* wr = (const ulonglong2*)(swc + (j * 4 + e) * 36);
                ulonglong2 w8 = wr[8];              // (wih0,wih1 | bias,0)
                ull a0a = fma2(w8.x, xa, w8.y);
                ull a0b = fma2(w8.x, xb, w8.y);
                ull a1a = 0ull, a1b = 0ull;
#pragma unroll
                for (int q = 0; q < 8; q++) {
                    ulonglong2 w = wr[q];           // LDS.128, 4-group broadcast
                    a0a = fma2(w.x, ha[2 * q + 0], a0a);
                    a1a = fma2(w.y, ha[2 * q + 1], a1a);
                    a0b = fma2(w.x, hb[2 * q + 0], a0b);
                    a1b = fma2(w.y, hb[2 * q + 1], a1b);
                }
                ull sa_ = add2(a0a, a1a);
                ull sb_ = add2(a0b, a1b);
                gate_a[e] = lo2(sa_) + hi2(sa_);
                gate_b[e] = lo2(sb_) + hi2(sb_);
            }
            float wo = swout[g * 8 + j];
            {
                float iv = sigm(gate_a[0]), fv = sigm(gate_a[1]);
                float gv = tanhx(gate_a[2]), ov = sigm(gate_a[3]);
                float cn = fmaf(fv, ca[j], iv * gv);
                ca[j] = cn;
                float hn = ov * tanhx(cn);
                hna[j] = hn;
                oa = fmaf(hn, wo, oa);
            }
            {
                float iv = sigm(gate_b[0]), fv = sigm(gate_b[1]);
                float gv = tanhx(gate_b[2]), ov = sigm(gate_b[3]);
                float cn = fmaf(fv, cb[j], iv * gv);
                cb[j] = cn;
                float hn = ov * tanhx(cn);
                hnb[j] = hn;
                ob = fmaf(hn, wo, ob);
            }
        }

        // ---- h exchange: every lane assembles the full 16 pairs per batch ----
        ull va[4], vb[4];
#pragma unroll
        for (int q2 = 0; q2 < 4; q2++) {
            va[q2] = pack2(hna[2 * q2], hna[2 * q2 + 1]);
            vb[q2] = pack2(hnb[2 * q2], hnb[2 * q2 + 1]);
        }
#pragma unroll
        for (int p = 0; p < 16; p++) {
            int src = (p >> 2) * 8 + s;             // same sub-lane, owning group
            ha[p] = __shfl_sync(0xffffffffu, va[p & 3], src);
            hb[p] = __shfl_sync(0xffffffffu, vb[p & 3], src);
        }

        // ---- output projection: cross-group reduce, group 0 stores ----
        oa += __shfl_xor_sync(0xffffffffu, oa, 8);
        oa += __shfl_xor_sync(0xffffffffu, oa, 16);
        ob += __shfl_xor_sync(0xffffffffu, ob, 8);
        ob += __shfl_xor_sync(0xffffffffu, ob, 16);
        if (g == 0) {
            op0[t] = oa + bo;
            op1[t] = ob + bo;
        }
    }
}

extern "C" void kernel_launch(void* const* d_in, const int* in_sizes, int n_in,
                              void* d_out, int out_size) {
    const float* x     = (const float*)d_in[0];
    const float* W_ih  = (const float*)d_in[1];
    const float* W_hh  = (const float*)d_in[2];
    const float* b_ih  = (const float*)d_in[3];
    const float* b_hh  = (const float*)d_in[4];
    const float* W_out = (const float*)d_in[5];
    const float* b_out = (const float*)d_in[6];
    const float* h0    = (const float*)d_in[7];
    const float* c0    = (const float*)d_in[8];
    float* out = (float*)d_out;

    // 32768 batches / 16 per warp = 2048 warps / 2 per block = 1024 blocks
    lsnn_kernel<<<1024, 64>>>(x, W_ih, W_hh, b_ih, b_hh,
                              W_out, b_out, h0, c0, out);
}

// round 4
// speedup vs baseline: 3.6528x; 2.3995x over previous
#include <cuda_runtime.h>
#include <cuda_bf16.h>
#include <cstdint>

#define T_LEN 50
typedef uint32_t u32;

// ---- mma.sync m16n8k16 bf16 (plain sm_80+ PTX -> legacy HMMA on sm_103) ----
__device__ __forceinline__ void mma16816(float* d, u32 a0, u32 a1, u32 a2, u32 a3,
                                         u32 b0, u32 b1) {
    asm volatile(
        "mma.sync.aligned.m16n8k16.row.col.f32.bf16.bf16.f32 "
        "{%0,%1,%2,%3},{%4,%5,%6,%7},{%8,%9},{%0,%1,%2,%3};"
        : "+f"(d[0]), "+f"(d[1]), "+f"(d[2]), "+f"(d[3])
        : "r"(a0), "r"(a1), "r"(a2), "r"(a3), "r"(b0), "r"(b1));
}

// ---- bf16 split helpers ----
__device__ __forceinline__ u32 bh_u(float v) {
    return (u32)__bfloat16_as_ushort(__float2bfloat16_rn(v));
}
__device__ __forceinline__ float bh_f(float v) {
    return __bfloat162float(__float2bfloat16_rn(v));
}

// ---- fast activations (MUFU, ~1e-7 rel err) ----
__device__ __forceinline__ float ex2f(float x) {
    float r; asm("ex2.approx.f32 %0,%1;" : "=f"(r) : "f"(x)); return r;
}
__device__ __forceinline__ float rcpf(float x) {
    float r; asm("rcp.approx.f32 %0,%1;" : "=f"(r) : "f"(x)); return r;
}
__device__ __forceinline__ float sigm(float x) {
    return rcpf(1.0f + ex2f(-1.4426950408889634f * x));
}
__device__ __forceinline__ float tanhx(float x) {
    return fmaf(2.0f, rcpf(1.0f + ex2f(-2.8853900817779268f * x)), -1.0f);
}

// Gate-column order: n = 32*gate + unit.  Warp handles 16 batches (m16);
// thread t (c=t%4, g=t/4) owns rows {g, g+8} and units {8m+2c+b}.
// D-frag / A-frag layouts line up so the recurrence never leaves registers.
__global__ void __launch_bounds__(128, 4) lsnn_kernel(
    const float* __restrict__ x,     // [B, T, 2]
    const float* __restrict__ W_ih,  // [128, 2]
    const float* __restrict__ W_hh,  // [128, 32]
    const float* __restrict__ b_ih,  // [128]
    const float* __restrict__ b_hh,  // [128]
    const float* __restrict__ W_out, // [1, 32]
    const float* __restrict__ b_out, // [1]
    const float* __restrict__ h0,    // [B, 32]
    const float* __restrict__ c0,    // [B, 32]
    float* __restrict__ out)         // [B, 50]
{
    // B-fragment table: 16 tiles x 32 lanes x 12 words (48B stride, conflict-free)
    __shared__ __align__(16) u32 sbf[512 * 12];   // 24 KB

    const int tid = threadIdx.x;

    // ---- one-time B-fragment build ----
    for (int eid = tid; eid < 512; eid += 128) {
        const int jj = eid >> 5, ln = eid & 31;
        const int cc = ln & 3, gg = ln >> 2;
        const int m = jj >> 2, e = jj & 3;
        const int n = 32 * e + 8 * m + gg;        // gate row in weights
        const float* wr = W_hh + n * 32;
        u32 w[12];
        const int ks = 2 * cc;
#pragma unroll
        for (int q = 0; q < 4; q++) {
            const int k0 = ks + 8 * q;
            float v0 = wr[k0], v1 = wr[k0 + 1];
            u32 h0u = bh_u(v0), h1u = bh_u(v1);
            u32 l0u = bh_u(v0 - bh_f(v0)), l1u = bh_u(v1 - bh_f(v1));
            w[q]     = h0u | (h1u << 16);
            w[4 + q] = l0u | (l1u << 16);
        }
        if (cc < 2) {                  // x-weight rows (hi paired, lo in b1)
            float wv = W_ih[n * 2 + cc];
            u32 hu = bh_u(wv);
            w[8] = hu | (hu << 16);
            w[9] = bh_u(wv - bh_f(wv));
        } else if (cc == 2) {          // bias rows (hi, lo) hit by ones-columns
            float bv = b_ih[n] + b_hh[n];
            w[8] = bh_u(bv) | (bh_u(bv - bh_f(bv)) << 16);
            w[9] = 0;
        } else { w[8] = 0; w[9] = 0; }
        w[10] = 0; w[11] = 0;
#pragma unroll
        for (int q = 0; q < 12; q++) sbf[eid * 12 + q] = w[q];
    }
    __syncthreads();

    const int lane = tid & 31, warp = tid >> 5;
    const int c = lane & 3, g = lane >> 2;
    const long b0i = (long)blockIdx.x * 64 + warp * 16 + g;  // row g
    const long b1i = b0i + 8;                                 // row g+8

    // ---- per-thread state ----
    float cst[16];                 // [m][row][b]
    u32 Ahi[2][4], Alo[2][4];      // h as A-fragments (kt0, kt1)
    float wo[8];
#pragma unroll
    for (int m = 0; m < 4; m++)
#pragma unroll
        for (int row = 0; row < 2; row++) {
            const long bb = row ? b1i : b0i;
            const int u0 = 8 * m + 2 * c;
            cst[m * 4 + row * 2 + 0] = c0[bb * 32 + u0];
            cst[m * 4 + row * 2 + 1] = c0[bb * 32 + u0 + 1];
            float hv0 = h0[bb * 32 + u0];
            float hv1 = h0[bb * 32 + u0 + 1];
            Ahi[m >> 1][(m & 1) * 2 + row] = bh_u(hv0) | (bh_u(hv1) << 16);
            Alo[m >> 1][(m & 1) * 2 + row] =
                bh_u(hv0 - bh_f(hv0)) | (bh_u(hv1 - bh_f(hv1)) << 16);
        }
#pragma unroll
    for (int m = 0; m < 4; m++) {
        wo[m * 2 + 0] = W_out[8 * m + 2 * c];
        wo[m * 2 + 1] = W_out[8 * m + 2 * c + 1];
    }
    const float bo = b_out[0];

    const float* xr0 = x + b0i * (T_LEN * 2);
    const float* xr1 = x + b1i * (T_LEN * 2);
    float2 xa = *(const float2*)xr0;
    float2 xb = *(const float2*)xr1;

    for (int t = 0; t < T_LEN; t++) {
        // ---- kt6 A-fragment: [x0h,x0l,x1h,x1l,1,1,0,0 | x0h,0,x1h,0,...] ----
        u32 Ax0, Ax1, Ax2, Ax3;
        if (c == 0) {
            Ax0 = bh_u(xa.x) | (bh_u(xa.x - bh_f(xa.x)) << 16);
            Ax1 = bh_u(xb.x) | (bh_u(xb.x - bh_f(xb.x)) << 16);
            Ax2 = bh_u(xa.x); Ax3 = bh_u(xb.x);
        } else if (c == 1) {
            Ax0 = bh_u(xa.y) | (bh_u(xa.y - bh_f(xa.y)) << 16);
            Ax1 = bh_u(xb.y) | (bh_u(xb.y - bh_f(xb.y)) << 16);
            Ax2 = bh_u(xa.y); Ax3 = bh_u(xb.y);
        } else if (c == 2) {
            Ax0 = 0x3F803F80u; Ax1 = 0x3F803F80u; Ax2 = 0; Ax3 = 0;
        } else { Ax0 = 0; Ax1 = 0; Ax2 = 0; Ax3 = 0; }

        if (t + 1 < T_LEN) {        // prefetch next x
            xa = *(const float2*)(xr0 + 2 * (t + 1));
            xb = *(const float2*)(xr1 + 2 * (t + 1));
        }

        u32 nAhi[2][4], nAlo[2][4];
        float oacc0 = 0.0f, oacc1 = 0.0f;

#pragma unroll
        for (int m = 0; m < 4; m++) {
            float D[4][4];
#pragma unroll
            for (int e = 0; e < 4; e++)
#pragma unroll
                for (int q = 0; q < 4; q++) D[e][q] = 0.0f;

#pragma unroll
            for (int e = 0; e < 4; e++) {
                const uint4* bp =
                    (const uint4*)&sbf[(((m * 4 + e) * 32) + lane) * 12];
                uint4 B0 = bp[0];   // hi: kt0 b0,b1 | kt1 b0,b1
                uint4 B1 = bp[1];   // lo
                uint4 B2 = bp[2];   // x/bias tile
                mma16816(D[e], Ahi[0][0], Ahi[0][1], Ahi[0][2], Ahi[0][3], B0.x, B0.y);
                mma16816(D[e], Ahi[1][0], Ahi[1][1], Ahi[1][2], Ahi[1][3], B0.z, B0.w);
                mma16816(D[e], Alo[0][0], Alo[0][1], Alo[0][2], Alo[0][3], B0.x, B0.y);
                mma16816(D[e], Alo[1][0], Alo[1][1], Alo[1][2], Alo[1][3], B0.z, B0.w);
                mma16816(D[e], Ahi[0][0], Ahi[0][1], Ahi[0][2], Ahi[0][3], B1.x, B1.y);
                mma16816(D[e], Ahi[1][0], Ahi[1][1], Ahi[1][2], Ahi[1][3], B1.z, B1.w);
                mma16816(D[e], Ax0, Ax1, Ax2, Ax3, B2.x, B2.y);
            }

            // ---- epilogue: gates -> c,h  (all thread-local) ----
#pragma unroll
            for (int row = 0; row < 2; row++) {
                u32 hiw = 0, low = 0;
#pragma unroll
                for (int b = 0; b < 2; b++) {
                    const int di = row * 2 + b;
                    float iv = sigm(D[0][di]);
                    float fv = sigm(D[1][di]);
                    float gv = tanhx(D[2][di]);
                    float ov = sigm(D[3][di]);
                    const int ci = m * 4 + row * 2 + b;
                    float cn = fmaf(fv, cst[ci], iv * gv);
                    cst[ci] = cn;
                    float hn = ov * tanhx(cn);
                    if (row == 0) oacc0 = fmaf(hn, wo[m * 2 + b], oacc0);
                    else          oacc1 = fmaf(hn, wo[m * 2 + b], oacc1);
                    u32 hu = bh_u(hn);
                    u32 lu = bh_u(hn - bh_f(hn));
                    hiw |= hu << (16 * b);
                    low |= lu << (16 * b);
                }
                nAhi[m >> 1][(m & 1) * 2 + row] = hiw;
                nAlo[m >> 1][(m & 1) * 2 + row] = low;
            }
        }

#pragma unroll
        for (int kt = 0; kt < 2; kt++)
#pragma unroll
            for (int q = 0; q < 4; q++) {
                Ahi[kt][q] = nAhi[kt][q];
                Alo[kt][q] = nAlo[kt][q];
            }

        // ---- output projection: reduce over c (lanes xor 1,2) ----
        oacc0 += __shfl_xor_sync(0xffffffffu, oacc0, 1);
        oacc0 += __shfl_xor_sync(0xffffffffu, oacc0, 2);
        oacc1 += __shfl_xor_sync(0xffffffffu, oacc1, 1);
        oacc1 += __shfl_xor_sync(0xffffffffu, oacc1, 2);
        if (c == 0) {
            out[b0i * T_LEN + t] = oacc0 + bo;
            out[b1i * T_LEN + t] = oacc1 + bo;
        }
    }
}

extern "C" void kernel_launch(void* const* d_in, const int* in_sizes, int n_in,
                              void* d_out, int out_size) {
    const float* x     = (const float*)d_in[0];
    const float* W_ih  = (const float*)d_in[1];
    const float* W_hh  = (const float*)d_in[2];
    const float* b_ih  = (const float*)d_in[3];
    const float* b_hh  = (const float*)d_in[4];
    const float* W_out = (const float*)d_in[5];
    const float* b_out = (const float*)d_in[6];
    const float* h0    = (const float*)d_in[7];
    const float* c0    = (const float*)d_in[8];
    float* out = (float*)d_out;

    // 32768 batches / 64 per CTA (4 warps x m16) = 512 CTAs
    lsnn_kernel<<<512, 128>>>(x, W_ih, W_hh, b_ih, b_hh,
                              W_out, b_out, h0, c0, out);
}

// round 5
// speedup vs baseline: 4.9392x; 1.3522x over previous
#include <cuda_runtime.h>
#include <cuda_bf16.h>
#include <cstdint>

#define T_LEN 50
typedef uint32_t u32;

// ---- mma.sync m16n8k16 bf16 (legacy HMMA path on sm_103) ----
__device__ __forceinline__ void mma16816(float* d, u32 a0, u32 a1, u32 a2, u32 a3,
                                         u32 b0, u32 b1) {
    asm volatile(
        "mma.sync.aligned.m16n8k16.row.col.f32.bf16.bf16.f32 "
        "{%0,%1,%2,%3},{%4,%5,%6,%7},{%8,%9},{%0,%1,%2,%3};"
        : "+f"(d[0]), "+f"(d[1]), "+f"(d[2]), "+f"(d[3])
        : "r"(a0), "r"(a1), "r"(a2), "r"(a3), "r"(b0), "r"(b1));
}
// first MMA of a chain: C = 0 (skips explicit D zero-init)
__device__ __forceinline__ void mma16816_z(float* d, u32 a0, u32 a1, u32 a2, u32 a3,
                                           u32 b0, u32 b1) {
    asm volatile(
        "mma.sync.aligned.m16n8k16.row.col.f32.bf16.bf16.f32 "
        "{%0,%1,%2,%3},{%4,%5,%6,%7},{%8,%9},{%10,%11,%12,%13};"
        : "=f"(d[0]), "=f"(d[1]), "=f"(d[2]), "=f"(d[3])
        : "r"(a0), "r"(a1), "r"(a2), "r"(a3), "r"(b0), "r"(b1),
          "f"(0.0f), "f"(0.0f), "f"(0.0f), "f"(0.0f));
}

// ---- bf16 helpers (setup only) ----
__device__ __forceinline__ u32 bh_u(float v) {
    return (u32)__bfloat16_as_ushort(__float2bfloat16_rn(v));
}
__device__ __forceinline__ float bh_f(float v) {
    return __bfloat162float(__float2bfloat16_rn(v));
}

// ---- fast math ----
__device__ __forceinline__ float ex2f(float x) {
    float r; asm("ex2.approx.f32 %0,%1;" : "=f"(r) : "f"(x)); return r;
}
__device__ __forceinline__ float rcpf(float x) {
    float r; asm("rcp.approx.f32 %0,%1;" : "=f"(r) : "f"(x)); return r;
}
__device__ __forceinline__ float tanhapx(float x) {
    float r; asm("tanh.approx.f32 %0,%1;" : "=f"(r) : "f"(x)); return r;
}
// exact-path tanh (value path: g gate handled via prescale; this is for tanh(c))
__device__ __forceinline__ float tanhx(float x) {
    return fmaf(2.0f, rcpf(1.0f + ex2f(-2.8853900817779268f * x)), -1.0f);
}
// truncation split: hi = top 16 bits, lo = exact remainder
__device__ __forceinline__ float trunc_hi(float v) {
    return __uint_as_float(__float_as_uint(v) & 0xFFFF0000u);
}
__device__ __forceinline__ u32 prmt_hi16(u32 a, u32 b) {
    u32 r; asm("prmt.b32 %0,%1,%2,%3;" : "=r"(r) : "r"(a), "r"(b), "n"(0x7632)); return r;
}
__device__ __forceinline__ u32 cvt_bf16x2(float hi_elem, float lo_elem) {
    u32 r; asm("cvt.rn.satfinite.bf16x2.f32 %0,%1,%2;" : "=r"(r) : "f"(hi_elem), "f"(lo_elem)); return r;
}

// Gate-column order n = 32*gate + unit. Warp = 16 batches; thread (c=l%4,g=l/4)
// owns rows {g,g+8}, units {8m+2c,8m+2c+1}. D-frag == next-step A-frag: the
// recurrence never leaves registers. Gates are PRESCALED in the weights:
// i,f,o by 0.5 (sigmoid via tanh.approx), g by -2*log2(e) (exact ex2 tanh).
__global__ void __launch_bounds__(128, 4) lsnn_kernel(
    const float* __restrict__ x,     // [B, T, 2]
    const float* __restrict__ W_ih,  // [128, 2]
    const float* __restrict__ W_hh,  // [128, 32]
    const float* __restrict__ b_ih,  // [128]
    const float* __restrict__ b_hh,  // [128]
    const float* __restrict__ W_out, // [1, 32]
    const float* __restrict__ b_out, // [1]
    const float* __restrict__ h0,    // [B, 32]
    const float* __restrict__ c0,    // [B, 32]
    float* __restrict__ out)         // [B, 50]
{
    // B-fragment table: 16 tiles x 32 lanes x 12 words (48B stride, conflict-free)
    __shared__ __align__(16) u32 sbf[512 * 12];   // 24 KB

    const int tid = threadIdx.x;

    // ---- one-time B-fragment build (prescaled) ----
    for (int eid = tid; eid < 512; eid += 128) {
        const int jj = eid >> 5, ln = eid & 31;
        const int cc = ln & 3, gg = ln >> 2;
        const int m = jj >> 2, e = jj & 3;
        const int n = 32 * e + 8 * m + gg;        // gate row in weights
        const float sc = (e == 2) ? -2.8853900817779268f : 0.5f;
        const float* wr = W_hh + n * 32;
        u32 w[12];
        const int ks = 2 * cc;
#pragma unroll
        for (int q = 0; q < 4; q++) {
            const int k0 = ks + 8 * q;
            float v0 = wr[k0] * sc, v1 = wr[k0 + 1] * sc;
            u32 h0u = bh_u(v0), h1u = bh_u(v1);
            u32 l0u = bh_u(v0 - bh_f(v0)), l1u = bh_u(v1 - bh_f(v1));
            w[q]     = h0u | (h1u << 16);
            w[4 + q] = l0u | (l1u << 16);
        }
        if (cc < 2) {                  // x-weight rows (hi paired, lo in b1)
            float wv = W_ih[n * 2 + cc] * sc;
            u32 hu = bh_u(wv);
            w[8] = hu | (hu << 16);
            w[9] = bh_u(wv - bh_f(wv));
        } else if (cc == 2) {          // bias rows (hi, lo) hit by ones-columns
            float bv = (b_ih[n] + b_hh[n]) * sc;
            w[8] = bh_u(bv) | (bh_u(bv - bh_f(bv)) << 16);
            w[9] = 0;
        } else { w[8] = 0; w[9] = 0; }
        w[10] = 0; w[11] = 0;
#pragma unroll
        for (int q = 0; q < 12; q++) sbf[eid * 12 + q] = w[q];
    }
    __syncthreads();

    const int lane = tid & 31, warp = tid >> 5;
    const int c = lane & 3, g = lane >> 2;
    const long b0i = (long)blockIdx.x * 64 + warp * 16 + g;  // row g
    const long b1i = b0i + 8;                                 // row g+8

    // per-thread shared base: tile loads at immediate offsets from here
    const uint4* bpt = (const uint4*)(sbf + lane * 12);

    // ---- per-thread state ----
    float cst[16];                 // [m][row][b]
    u32 Ahi[2][4], Alo[2][4];      // h as A-fragments (kt0, kt1)
    float wo[8];
#pragma unroll
    for (int m = 0; m < 4; m++)
#pragma unroll
        for (int row = 0; row < 2; row++) {
            const long bb = row ? b1i : b0i;
            const int u0 = 8 * m + 2 * c;
            cst[m * 4 + row * 2 + 0] = c0[bb * 32 + u0];
            cst[m * 4 + row * 2 + 1] = c0[bb * 32 + u0 + 1];
            float hv0 = h0[bb * 32 + u0];
            float hv1 = h0[bb * 32 + u0 + 1];
            Ahi[m >> 1][(m & 1) * 2 + row] = bh_u(hv0) | (bh_u(hv1) << 16);
            Alo[m >> 1][(m & 1) * 2 + row] =
                bh_u(hv0 - bh_f(hv0)) | (bh_u(hv1 - bh_f(hv1)) << 16);
        }
#pragma unroll
    for (int m = 0; m < 4; m++) {
        wo[m * 2 + 0] = W_out[8 * m + 2 * c];
        wo[m * 2 + 1] = W_out[8 * m + 2 * c + 1];
    }
    const float bo = b_out[0];

    const float* xr0 = x + b0i * (T_LEN * 2);
    const float* xr1 = x + b1i * (T_LEN * 2);
    float2 xa = *(const float2*)xr0;
    float2 xb = *(const float2*)xr1;

    for (int t = 0; t < T_LEN; t++) {
        // ---- x/bias A-fragment (kt6): truncation split ----
        u32 Ax0, Ax1, Ax2, Ax3;
        if (c == 0) {
            u32 u0b = __float_as_uint(xa.x), u1b = __float_as_uint(xb.x);
            float l0 = xa.x - trunc_hi(xa.x), l1 = xb.x - trunc_hi(xb.x);
            Ax0 = (u0b >> 16) | (bh_u(l0) << 16);
            Ax1 = (u1b >> 16) | (bh_u(l1) << 16);
            Ax2 = u0b >> 16; Ax3 = u1b >> 16;
        } else if (c == 1) {
            u32 u0b = __float_as_uint(xa.y), u1b = __float_as_uint(xb.y);
            float l0 = xa.y - trunc_hi(xa.y), l1 = xb.y - trunc_hi(xb.y);
            Ax0 = (u0b >> 16) | (bh_u(l0) << 16);
            Ax1 = (u1b >> 16) | (bh_u(l1) << 16);
            Ax2 = u0b >> 16; Ax3 = u1b >> 16;
        } else if (c == 2) {
            Ax0 = 0x3F803F80u; Ax1 = 0x3F803F80u; Ax2 = 0; Ax3 = 0;
        } else { Ax0 = 0; Ax1 = 0; Ax2 = 0; Ax3 = 0; }

        if (t + 1 < T_LEN) {        // prefetch next x
            xa = *(const float2*)(xr0 + 2 * (t + 1));
            xb = *(const float2*)(xr1 + 2 * (t + 1));
        }

        u32 nAhi[2][4], nAlo[2][4];
        float oacc0 = 0.0f, oacc1 = 0.0f;

#pragma unroll
        for (int m = 0; m < 4; m++) {
            float D[4][4];
#pragma unroll
            for (int e = 0; e < 4; e++) {
                const uint4* bp = bpt + (m * 4 + e) * 96;  // 32 lanes * 3 uint4
                uint4 B0 = bp[0];   // hi: kt0 b0,b1 | kt1 b0,b1
                uint4 B1 = bp[1];   // lo
                uint4 B2 = bp[2];   // x/bias tile
                mma16816_z(D[e], Ax0, Ax1, Ax2, Ax3, B2.x, B2.y);
                mma16816(D[e], Ahi[0][0], Ahi[0][1], Ahi[0][2], Ahi[0][3], B0.x, B0.y);
                mma16816(D[e], Ahi[1][0], Ahi[1][1], Ahi[1][2], Ahi[1][3], B0.z, B0.w);
                mma16816(D[e], Alo[0][0], Alo[0][1], Alo[0][2], Alo[0][3], B0.x, B0.y);
                mma16816(D[e], Alo[1][0], Alo[1][1], Alo[1][2], Alo[1][3], B0.z, B0.w);
                mma16816(D[e], Ahi[0][0], Ahi[0][1], Ahi[0][2], Ahi[0][3], B1.x, B1.y);
                mma16816(D[e], Ahi[1][0], Ahi[1][1], Ahi[1][2], Ahi[1][3], B1.z, B1.w);
            }

            // ---- epilogue: gates -> c,h (thread-local) ----
#pragma unroll
            for (int row = 0; row < 2; row++) {
                float hn[2];
#pragma unroll
                for (int b = 0; b < 2; b++) {
                    const int di = row * 2 + b;
                    float iv = fmaf(0.5f, tanhapx(D[0][di]), 0.5f);
                    float fv = fmaf(0.5f, tanhapx(D[1][di]), 0.5f);
                    float gv = fmaf(2.0f, rcpf(1.0f + ex2f(D[2][di])), -1.0f);
                    float ov = fmaf(0.5f, tanhapx(D[3][di]), 0.5f);
                    const int ci = m * 4 + row * 2 + b;
                    float cn = fmaf(fv, cst[ci], iv * gv);
                    cst[ci] = cn;
                    hn[b] = ov * tanhx(cn);
                    if (row == 0) oacc0 = fmaf(hn[b], wo[m * 2 + b], oacc0);
                    else          oacc1 = fmaf(hn[b], wo[m * 2 + b], oacc1);
                }
                u32 ub0 = __float_as_uint(hn[0]);
                u32 ub1 = __float_as_uint(hn[1]);
                nAhi[m >> 1][(m & 1) * 2 + row] = prmt_hi16(ub0, ub1);
                float l0 = hn[0] - trunc_hi(hn[0]);
                float l1 = hn[1] - trunc_hi(hn[1]);
                nAlo[m >> 1][(m & 1) * 2 + row] = cvt_bf16x2(l1, l0);
            }
        }

#pragma unroll
        for (int kt = 0; kt < 2; kt++)
#pragma unroll
            for (int q = 0; q < 4; q++) {
                Ahi[kt][q] = nAhi[kt][q];
                Alo[kt][q] = nAlo[kt][q];
            }

        // ---- output projection: reduce over c (lanes xor 1,2) ----
        oacc0 += __shfl_xor_sync(0xffffffffu, oacc0, 1);
        oacc0 += __shfl_xor_sync(0xffffffffu, oacc0, 2);
        oacc1 += __shfl_xor_sync(0xffffffffu, oacc1, 1);
        oacc1 += __shfl_xor_sync(0xffffffffu, oacc1, 2);
        if (c == 0) {
            out[b0i * T_LEN + t] = oacc0 + bo;
            out[b1i * T_LEN + t] = oacc1 + bo;
        }
    }
}

extern "C" void kernel_launch(void* const* d_in, const int* in_sizes, int n_in,
                              void* d_out, int out_size) {
    const float* x     = (const float*)d_in[0];
    const float* W_ih  = (const float*)d_in[1];
    const float* W_hh  = (const float*)d_in[2];
    const float* b_ih  = (const float*)d_in[3];
    const float* b_hh  = (const float*)d_in[4];
    const float* W_out = (const float*)d_in[5];
    const float* b_out = (const float*)d_in[6];
    const float* h0    = (const float*)d_in[7];
    const float* c0    = (const float*)d_in[8];
    float* out = (float*)d_out;

    // 32768 batches / 64 per CTA (4 warps x m16) = 512 CTAs
    lsnn_kernel<<<512, 128>>>(x, W_ih, W_hh, b_ih, b_hh,
                              W_out, b_out, h0, c0, out);
}

// round 6
// speedup vs baseline: 4.9401x; 1.0002x over previous
#include <cuda_runtime.h>
#include <cuda_bf16.h>
#include <cstdint>

#define T_LEN 50
typedef uint32_t u32;

// ---- mma.sync m16n8k16 bf16 (legacy HMMA path on sm_103) ----
__device__ __forceinline__ void mma16816(float* d, u32 a0, u32 a1, u32 a2, u32 a3,
                                         u32 b0, u32 b1) {
    asm volatile(
        "mma.sync.aligned.m16n8k16.row.col.f32.bf16.bf16.f32 "
        "{%0,%1,%2,%3},{%4,%5,%6,%7},{%8,%9},{%0,%1,%2,%3};"
        : "+f"(d[0]), "+f"(d[1]), "+f"(d[2]), "+f"(d[3])
        : "r"(a0), "r"(a1), "r"(a2), "r"(a3), "r"(b0), "r"(b1));
}
// first MMA of a chain: C = 0 (skips explicit D zero-init)
__device__ __forceinline__ void mma16816_z(float* d, u32 a0, u32 a1, u32 a2, u32 a3,
                                           u32 b0, u32 b1) {
    asm volatile(
        "mma.sync.aligned.m16n8k16.row.col.f32.bf16.bf16.f32 "
        "{%0,%1,%2,%3},{%4,%5,%6,%7},{%8,%9},{%10,%11,%12,%13};"
        : "=f"(d[0]), "=f"(d[1]), "=f"(d[2]), "=f"(d[3])
        : "r"(a0), "r"(a1), "r"(a2), "r"(a3), "r"(b0), "r"(b1),
          "f"(0.0f), "f"(0.0f), "f"(0.0f), "f"(0.0f));
}

// ---- bf16 helpers (setup only) ----
__device__ __forceinline__ u32 bh_u(float v) {
    return (u32)__bfloat16_as_ushort(__float2bfloat16_rn(v));
}
__device__ __forceinline__ float bh_f(float v) {
    return __bfloat162float(__float2bfloat16_rn(v));
}

// ---- fast math ----
__device__ __forceinline__ float ex2f(float x) {
    float r; asm("ex2.approx.f32 %0,%1;" : "=f"(r) : "f"(x)); return r;
}
__device__ __forceinline__ float rcpf(float x) {
    float r; asm("rcp.approx.f32 %0,%1;" : "=f"(r) : "f"(x)); return r;
}
__device__ __forceinline__ float tanhapx(float x) {
    float r; asm("tanh.approx.f32 %0,%1;" : "=f"(r) : "f"(x)); return r;
}
// exact-path tanh (value path: g gate handled via prescale; this is for tanh(c))
__device__ __forceinline__ float tanhx(float x) {
    return fmaf(2.0f, rcpf(1.0f + ex2f(-2.8853900817779268f * x)), -1.0f);
}
// truncation split: hi = top 16 bits, lo = exact remainder
__device__ __forceinline__ float trunc_hi(float v) {
    return __uint_as_float(__float_as_uint(v) & 0xFFFF0000u);
}
__device__ __forceinline__ u32 prmt_hi16(u32 a, u32 b) {
    u32 r; asm("prmt.b32 %0,%1,%2,%3;" : "=r"(r) : "r"(a), "r"(b), "n"(0x7632)); return r;
}
__device__ __forceinline__ u32 cvt_bf16x2(float hi_elem, float lo_elem) {
    u32 r; asm("cvt.rn.satfinite.bf16x2.f32 %0,%1,%2;" : "=r"(r) : "f"(hi_elem), "f"(lo_elem)); return r;
}

// Gate-column order n = 32*gate + unit. Warp = 16 batches; thread (c=l%4,g=l/4)
// owns rows {g,g+8}, units {8m+2c,8m+2c+1}. D-frag == next-step A-frag: the
// recurrence never leaves registers. Gates are PRESCALED in the weights:
// i,f,o by 0.5 (sigmoid via tanh.approx), g by -2*log2(e) (exact ex2 tanh).
__global__ void __launch_bounds__(128, 4) lsnn_kernel(
    const float* __restrict__ x,     // [B, T, 2]
    const float* __restrict__ W_ih,  // [128, 2]
    const float* __restrict__ W_hh,  // [128, 32]
    const float* __restrict__ b_ih,  // [128]
    const float* __restrict__ b_hh,  // [128]
    const float* __restrict__ W_out, // [1, 32]
    const float* __restrict__ b_out, // [1]
    const float* __restrict__ h0,    // [B, 32]
    const float* __restrict__ c0,    // [B, 32]
    float* __restrict__ out)         // [B, 50]
{
    // B-fragment table: 16 tiles x 32 lanes x 12 words (48B stride, conflict-free)
    __shared__ __align__(16) u32 sbf[512 * 12];   // 24 KB

    const int tid = threadIdx.x;

    // ---- one-time B-fragment build (prescaled) ----
    for (int eid = tid; eid < 512; eid += 128) {
        const int jj = eid >> 5, ln = eid & 31;
        const int cc = ln & 3, gg = ln >> 2;
        const int m = jj >> 2, e = jj & 3;
        const int n = 32 * e + 8 * m + gg;        // gate row in weights
        const float sc = (e == 2) ? -2.8853900817779268f : 0.5f;
        const float* wr = W_hh + n * 32;
        u32 w[12];
        const int ks = 2 * cc;
#pragma unroll
        for (int q = 0; q < 4; q++) {
            const int k0 = ks + 8 * q;
            float v0 = wr[k0] * sc, v1 = wr[k0 + 1] * sc;
            u32 h0u = bh_u(v0), h1u = bh_u(v1);
            u32 l0u = bh_u(v0 - bh_f(v0)), l1u = bh_u(v1 - bh_f(v1));
            w[q]     = h0u | (h1u << 16);
            w[4 + q] = l0u | (l1u << 16);
        }
        if (cc < 2) {                  // x-weight rows (hi paired, lo in b1)
            float wv = W_ih[n * 2 + cc] * sc;
            u32 hu = bh_u(wv);
            w[8] = hu | (hu << 16);
            w[9] = bh_u(wv - bh_f(wv));
        } else if (cc == 2) {          // bias rows (hi, lo) hit by ones-columns
            float bv = (b_ih[n] + b_hh[n]) * sc;
            w[8] = bh_u(bv) | (bh_u(bv - bh_f(bv)) << 16);
            w[9] = 0;
        } else { w[8] = 0; w[9] = 0; }
        w[10] = 0; w[11] = 0;
#pragma unroll
        for (int q = 0; q < 12; q++) sbf[eid * 12 + q] = w[q];
    }
    __syncthreads();

    const int lane = tid & 31, warp = tid >> 5;
    const int c = lane & 3, g = lane >> 2;
    const long b0i = (long)blockIdx.x * 64 + warp * 16 + g;  // row g
    const long b1i = b0i + 8;                                 // row g+8

    // per-thread shared base: tile loads at immediate offsets from here
    const uint4* bpt = (const uint4*)(sbf + lane * 12);

    // ---- per-thread state ----
    float cst[16];                 // [m][row][b]
    u32 Ahi[2][4], Alo[2][4];      // h as A-fragments (kt0, kt1)
    float wo[8];
#pragma unroll
    for (int m = 0; m < 4; m++)
#pragma unroll
        for (int row = 0; row < 2; row++) {
            const long bb = row ? b1i : b0i;
            const int u0 = 8 * m + 2 * c;
            cst[m * 4 + row * 2 + 0] = c0[bb * 32 + u0];
            cst[m * 4 + row * 2 + 1] = c0[bb * 32 + u0 + 1];
            float hv0 = h0[bb * 32 + u0];
            float hv1 = h0[bb * 32 + u0 + 1];
            Ahi[m >> 1][(m & 1) * 2 + row] = bh_u(hv0) | (bh_u(hv1) << 16);
            Alo[m >> 1][(m & 1) * 2 + row] =
                bh_u(hv0 - bh_f(hv0)) | (bh_u(hv1 - bh_f(hv1)) << 16);
        }
#pragma unroll
    for (int m = 0; m < 4; m++) {
        wo[m * 2 + 0] = W_out[8 * m + 2 * c];
        wo[m * 2 + 1] = W_out[8 * m + 2 * c + 1];
    }
    const float bo = b_out[0];

    const float* xr0 = x + b0i * (T_LEN * 2);
    const float* xr1 = x + b1i * (T_LEN * 2);
    float2 xa = *(const float2*)xr0;
    float2 xb = *(const float2*)xr1;

    for (int t = 0; t < T_LEN; t++) {
        // ---- x/bias A-fragment (kt6): truncation split ----
        u32 Ax0, Ax1, Ax2, Ax3;
        if (c == 0) {
            u32 u0b = __float_as_uint(xa.x), u1b = __float_as_uint(xb.x);
            float l0 = xa.x - trunc_hi(xa.x), l1 = xb.x - trunc_hi(xb.x);
            Ax0 = (u0b >> 16) | (bh_u(l0) << 16);
            Ax1 = (u1b >> 16) | (bh_u(l1) << 16);
            Ax2 = u0b >> 16; Ax3 = u1b >> 16;
        } else if (c == 1) {
            u32 u0b = __float_as_uint(xa.y), u1b = __float_as_uint(xb.y);
            float l0 = xa.y - trunc_hi(xa.y), l1 = xb.y - trunc_hi(xb.y);
            Ax0 = (u0b >> 16) | (bh_u(l0) << 16);
            Ax1 = (u1b >> 16) | (bh_u(l1) << 16);
            Ax2 = u0b >> 16; Ax3 = u1b >> 16;
        } else if (c == 2) {
            Ax0 = 0x3F803F80u; Ax1 = 0x3F803F80u; Ax2 = 0; Ax3 = 0;
        } else { Ax0 = 0; Ax1 = 0; Ax2 = 0; Ax3 = 0; }

        if (t + 1 < T_LEN) {        // prefetch next x
            xa = *(const float2*)(xr0 + 2 * (t + 1));
            xb = *(const float2*)(xr1 + 2 * (t + 1));
        }

        u32 nAhi[2][4], nAlo[2][4];
        float oacc0 = 0.0f, oacc1 = 0.0f;

#pragma unroll
        for (int m = 0; m < 4; m++) {
            float D[4][4];
#pragma unroll
            for (int e = 0; e < 4; e++) {
                const uint4* bp = bpt + (m * 4 + e) * 96;  // 32 lanes * 3 uint4
                uint4 B0 = bp[0];   // hi: kt0 b0,b1 | kt1 b0,b1
                uint4 B1 = bp[1];   // lo
                uint4 B2 = bp[2];   // x/bias tile
                mma16816_z(D[e], Ax0, Ax1, Ax2, Ax3, B2.x, B2.y);
                mma16816(D[e], Ahi[0][0], Ahi[0][1], Ahi[0][2], Ahi[0][3], B0.x, B0.y);
                mma16816(D[e], Ahi[1][0], Ahi[1][1], Ahi[1][2], Ahi[1][3], B0.z, B0.w);
                mma16816(D[e], Alo[0][0], Alo[0][1], Alo[0][2], Alo[0][3], B0.x, B0.y);
                mma16816(D[e], Alo[1][0], Alo[1][1], Alo[1][2], Alo[1][3], B0.z, B0.w);
                mma16816(D[e], Ahi[0][0], Ahi[0][1], Ahi[0][2], Ahi[0][3], B1.x, B1.y);
                mma16816(D[e], Ahi[1][0], Ahi[1][1], Ahi[1][2], Ahi[1][3], B1.z, B1.w);
            }

            // ---- epilogue: gates -> c,h (thread-local) ----
#pragma unroll
            for (int row = 0; row < 2; row++) {
                float hn[2];
#pragma unroll
                for (int b = 0; b < 2; b++) {
                    const int di = row * 2 + b;
                    float iv = fmaf(0.5f, tanhapx(D[0][di]), 0.5f);
                    float fv = fmaf(0.5f, tanhapx(D[1][di]), 0.5f);
                    float gv = fmaf(2.0f, rcpf(1.0f + ex2f(D[2][di])), -1.0f);
                    float ov = fmaf(0.5f, tanhapx(D[3][di]), 0.5f);
                    const int ci = m * 4 + row * 2 + b;
                    float cn = fmaf(fv, cst[ci], iv * gv);
                    cst[ci] = cn;
                    hn[b] = ov * tanhx(cn);
                    if (row == 0) oacc0 = fmaf(hn[b], wo[m * 2 + b], oacc0);
                    else          oacc1 = fmaf(hn[b], wo[m * 2 + b], oacc1);
                }
                u32 ub0 = __float_as_uint(hn[0]);
                u32 ub1 = __float_as_uint(hn[1]);
                nAhi[m >> 1][(m & 1) * 2 + row] = prmt_hi16(ub0, ub1);
                float l0 = hn[0] - trunc_hi(hn[0]);
                float l1 = hn[1] - trunc_hi(hn[1]);
                nAlo[m >> 1][(m & 1) * 2 + row] = cvt_bf16x2(l1, l0);
            }
        }

#pragma unroll
        for (int kt = 0; kt < 2; kt++)
#pragma unroll
            for (int q = 0; q < 4; q++) {
                Ahi[kt][q] = nAhi[kt][q];
                Alo[kt][q] = nAlo[kt][q];
            }

        // ---- output projection: reduce over c (lanes xor 1,2) ----
        oacc0 += __shfl_xor_sync(0xffffffffu, oacc0, 1);
        oacc0 += __shfl_xor_sync(0xffffffffu, oacc0, 2);
        oacc1 += __shfl_xor_sync(0xffffffffu, oacc1, 1);
        oacc1 += __shfl_xor_sync(0xffffffffu, oacc1, 2);
        if (c == 0) {
            out[b0i * T_LEN + t] = oacc0 + bo;
            out[b1i * T_LEN + t] = oacc1 + bo;
        }
    }
}

extern "C" void kernel_launch(void* const* d_in, const int* in_sizes, int n_in,
                              void* d_out, int out_size) {
    const float* x     = (const float*)d_in[0];
    const float* W_ih  = (const float*)d_in[1];
    const float* W_hh  = (const float*)d_in[2];
    const float* b_ih  = (const float*)d_in[3];
    const float* b_hh  = (const float*)d_in[4];
    const float* W_out = (const float*)d_in[5];
    const float* b_out = (const float*)d_in[6];
    const float* h0    = (const float*)d_in[7];
    const float* c0    = (const float*)d_in[8];
    float* out = (float*)d_out;

    // 32768 batches / 64 per CTA (4 warps x m16) = 512 CTAs
    lsnn_kernel<<<512, 128>>>(x, W_ih, W_hh, b_ih, b_hh,
                              W_out, b_out, h0, c0, out);
}

// round 7
// speedup vs baseline: 5.9264x; 1.1996x over previous
#include <cuda_runtime.h>
#include <cuda_bf16.h>
#include <cstdint>

#define T_LEN 50
typedef uint32_t u32;

// ---- mma.sync m16n8k16 bf16 (legacy HMMA path on sm_103) ----
__device__ __forceinline__ void mma16816(float* d, u32 a0, u32 a1, u32 a2, u32 a3,
                                         u32 b0, u32 b1) {
    asm volatile(
        "mma.sync.aligned.m16n8k16.row.col.f32.bf16.bf16.f32 "
        "{%0,%1,%2,%3},{%4,%5,%6,%7},{%8,%9},{%0,%1,%2,%3};"
        : "+f"(d[0]), "+f"(d[1]), "+f"(d[2]), "+f"(d[3])
        : "r"(a0), "r"(a1), "r"(a2), "r"(a3), "r"(b0), "r"(b1));
}
__device__ __forceinline__ void mma16816_z(float* d, u32 a0, u32 a1, u32 a2, u32 a3,
                                           u32 b0, u32 b1) {
    asm volatile(
        "mma.sync.aligned.m16n8k16.row.col.f32.bf16.bf16.f32 "
        "{%0,%1,%2,%3},{%4,%5,%6,%7},{%8,%9},{%10,%11,%12,%13};"
        : "=f"(d[0]), "=f"(d[1]), "=f"(d[2]), "=f"(d[3])
        : "r"(a0), "r"(a1), "r"(a2), "r"(a3), "r"(b0), "r"(b1),
          "f"(0.0f), "f"(0.0f), "f"(0.0f), "f"(0.0f));
}

// ---- bf16 helpers (setup only) ----
__device__ __forceinline__ u32 bh_u(float v) {
    return (u32)__bfloat16_as_ushort(__float2bfloat16_rn(v));
}
__device__ __forceinline__ float bh_f(float v) {
    return __bfloat162float(__float2bfloat16_rn(v));
}

// ---- fast math ----
__device__ __forceinline__ float tanhapx(float x) {
    float r; asm("tanh.approx.f32 %0,%1;" : "=f"(r) : "f"(x)); return r;
}
__device__ __forceinline__ float trunc_hi(float v) {
    return __uint_as_float(__float_as_uint(v) & 0xFFFF0000u);
}
__device__ __forceinline__ u32 prmt_hi16(u32 a, u32 b) {
    u32 r; asm("prmt.b32 %0,%1,%2,%3;" : "=r"(r) : "r"(a), "r"(b), "n"(0x7632)); return r;
}
__device__ __forceinline__ u32 cvt_bf16x2(float hi_elem, float lo_elem) {
    u32 r; asm("cvt.rn.satfinite.bf16x2.f32 %0,%1,%2;" : "=r"(r) : "f"(hi_elem), "f"(lo_elem)); return r;
}

// Gate-column order n = 32*gate + unit. Warp = 32 batches = 2 row-blocks (rb) of
// m16; thread (c=l%4,g=l/4) owns rows {g,g+8} per block, units {8m+2c,8m+2c+1}.
// Each B-fragment LDS feeds both row-blocks (2x MMA per load). Gates prescaled:
// i,f,o by 0.5 (sigmoid = 0.5+0.5*tanh), g by 1.0 (tanh.approx direct).
__global__ void __launch_bounds__(64, 4) lsnn_kernel(
    const float* __restrict__ x,     // [B, T, 2]
    const float* __restrict__ W_ih,  // [128, 2]
    const float* __restrict__ W_hh,  // [128, 32]
    const float* __restrict__ b_ih,  // [128]
    const float* __restrict__ b_hh,  // [128]
    const float* __restrict__ W_out, // [1, 32]
    const float* __restrict__ b_out, // [1]
    const float* __restrict__ h0,    // [B, 32]
    const float* __restrict__ c0,    // [B, 32]
    float* __restrict__ out)         // [B, 50]
{
    // B-fragment table: 16 tiles x 32 lanes x 12 words (48B stride, LDS.128-conflict-free)
    __shared__ __align__(16) u32 sbf[512 * 12];   // 24 KB

    const int tid = threadIdx.x;

    // ---- one-time B-fragment build (prescaled) ----
    for (int eid = tid; eid < 512; eid += 64) {
        const int jj = eid >> 5, ln = eid & 31;
        const int cc = ln & 3, gg = ln >> 2;
        const int m = jj >> 2, e = jj & 3;
        const int n = 32 * e + 8 * m + gg;        // gate row in weights
        const float sc = (e == 2) ? 1.0f : 0.5f;
        const float* wr = W_hh + n * 32;
        u32 w[12];
        const int ks = 2 * cc;
#pragma unroll
        for (int q = 0; q < 4; q++) {
            const int k0 = ks + 8 * q;
            float v0 = wr[k0] * sc, v1 = wr[k0 + 1] * sc;
            w[q]     = bh_u(v0) | (bh_u(v1) << 16);
            w[4 + q] = bh_u(v0 - bh_f(v0)) | (bh_u(v1 - bh_f(v1)) << 16);
        }
        if (cc < 2) {                  // x-weight rows (hi paired, lo in b1)
            float wv = W_ih[n * 2 + cc] * sc;
            u32 hu = bh_u(wv);
            w[8] = hu | (hu << 16);
            w[9] = bh_u(wv - bh_f(wv));
        } else if (cc == 2) {          // bias rows (hi, lo) hit by ones-columns
            float bv = (b_ih[n] + b_hh[n]) * sc;
            w[8] = bh_u(bv) | (bh_u(bv - bh_f(bv)) << 16);
            w[9] = 0;
        } else { w[8] = 0; w[9] = 0; }
        w[10] = 0; w[11] = 0;
#pragma unroll
        for (int q = 0; q < 12; q++) sbf[eid * 12 + q] = w[q];
    }
    __syncthreads();

    const int lane = tid & 31, warp = tid >> 5;
    const int c = lane & 3, g = lane >> 2;
    const long base = (long)blockIdx.x * 64 + warp * 32;

    const uint4* bpt = (const uint4*)(sbf + lane * 12);

    long brow[2][2];
    brow[0][0] = base + g;      brow[0][1] = base + g + 8;
    brow[1][0] = base + 16 + g; brow[1][1] = base + 24 + g;

    // ---- per-thread state: 2 row-blocks ----
    float cst[2][16];
    u32 Ahi[2][2][4], Alo[2][2][4];
    float wo[8];
#pragma unroll
    for (int rb = 0; rb < 2; rb++)
#pragma unroll
        for (int m = 0; m < 4; m++)
#pragma unroll
            for (int row = 0; row < 2; row++) {
                const long bb = brow[rb][row];
                const int u0 = 8 * m + 2 * c;
                cst[rb][m * 4 + row * 2 + 0] = c0[bb * 32 + u0];
                cst[rb][m * 4 + row * 2 + 1] = c0[bb * 32 + u0 + 1];
                float hv0 = h0[bb * 32 + u0];
                float hv1 = h0[bb * 32 + u0 + 1];
                Ahi[rb][m >> 1][(m & 1) * 2 + row] = bh_u(hv0) | (bh_u(hv1) << 16);
                Alo[rb][m >> 1][(m & 1) * 2 + row] =
                    bh_u(hv0 - bh_f(hv0)) | (bh_u(hv1 - bh_f(hv1)) << 16);
            }
#pragma unroll
    for (int m = 0; m < 4; m++) {
        wo[m * 2 + 0] = W_out[8 * m + 2 * c];
        wo[m * 2 + 1] = W_out[8 * m + 2 * c + 1];
    }
    const float bo = b_out[0];

    const float* xr[2][2];
    float2 xv[2][2];
#pragma unroll
    for (int rb = 0; rb < 2; rb++)
#pragma unroll
        for (int row = 0; row < 2; row++) {
            xr[rb][row] = x + brow[rb][row] * (T_LEN * 2);
            xv[rb][row] = *(const float2*)xr[rb][row];
        }

    for (int t = 0; t < T_LEN; t++) {
        // ---- x/bias A-fragments per row-block (truncation split) ----
        u32 Ax[2][4];
#pragma unroll
        for (int rb = 0; rb < 2; rb++) {
            float xa_ = (c == 0) ? xv[rb][0].x : xv[rb][0].y;
            float xb_ = (c == 0) ? xv[rb][1].x : xv[rb][1].y;
            if (c < 2) {
                u32 u0b = __float_as_uint(xa_), u1b = __float_as_uint(xb_);
                float l0 = xa_ - trunc_hi(xa_), l1 = xb_ - trunc_hi(xb_);
                Ax[rb][0] = (u0b >> 16) | (bh_u(l0) << 16);
                Ax[rb][1] = (u1b >> 16) | (bh_u(l1) << 16);
                Ax[rb][2] = u0b >> 16; Ax[rb][3] = u1b >> 16;
            } else if (c == 2) {
                Ax[rb][0] = 0x3F803F80u; Ax[rb][1] = 0x3F803F80u;
                Ax[rb][2] = 0; Ax[rb][3] = 0;
            } else { Ax[rb][0] = 0; Ax[rb][1] = 0; Ax[rb][2] = 0; Ax[rb][3] = 0; }
        }

        if (t + 1 < T_LEN) {        // prefetch next x
#pragma unroll
            for (int rb = 0; rb < 2; rb++)
#pragma unroll
                for (int row = 0; row < 2; row++)
                    xv[rb][row] = *(const float2*)(xr[rb][row] + 2 * (t + 1));
        }

        u32 nAhi[2][2][4], nAlo[2][2][4];
        float oacc[2][2] = {{0.0f, 0.0f}, {0.0f, 0.0f}};

#pragma unroll
        for (int m = 0; m < 4; m++) {
            float D[2][4][4];
#pragma unroll
            for (int e = 0; e < 4; e++) {
                const uint4* bp = bpt + (m * 4 + e) * 96;  // 32 lanes * 3 uint4
                uint4 B0 = bp[0];   // hi: kt0 b0,b1 | kt1 b0,b1
                uint4 B1 = bp[1];   // lo
                uint4 B2 = bp[2];   // x/bias tile
#pragma unroll
                for (int rb = 0; rb < 2; rb++) {
                    mma16816_z(D[rb][e], Ax[rb][0], Ax[rb][1], Ax[rb][2], Ax[rb][3], B2.x, B2.y);
                    mma16816(D[rb][e], Ahi[rb][0][0], Ahi[rb][0][1], Ahi[rb][0][2], Ahi[rb][0][3], B0.x, B0.y);
                    mma16816(D[rb][e], Ahi[rb][1][0], Ahi[rb][1][1], Ahi[rb][1][2], Ahi[rb][1][3], B0.z, B0.w);
                    mma16816(D[rb][e], Alo[rb][0][0], Alo[rb][0][1], Alo[rb][0][2], Alo[rb][0][3], B0.x, B0.y);
                    mma16816(D[rb][e], Alo[rb][1][0], Alo[rb][1][1], Alo[rb][1][2], Alo[rb][1][3], B0.z, B0.w);
                    mma16816(D[rb][e], Ahi[rb][0][0], Ahi[rb][0][1], Ahi[rb][0][2], Ahi[rb][0][3], B1.x, B1.y);
                    mma16816(D[rb][e], Ahi[rb][1][0], Ahi[rb][1][1], Ahi[rb][1][2], Ahi[rb][1][3], B1.z, B1.w);
                }
            }

            // ---- epilogue: gates -> c,h (thread-local) ----
#pragma unroll
            for (int rb = 0; rb < 2; rb++)
#pragma unroll
                for (int row = 0; row < 2; row++) {
                    float hn[2];
#pragma unroll
                    for (int b = 0; b < 2; b++) {
                        const int di = row * 2 + b;
                        float iv = fmaf(0.5f, tanhapx(D[rb][0][di]), 0.5f);
                        float fv = fmaf(0.5f, tanhapx(D[rb][1][di]), 0.5f);
                        float gv = tanhapx(D[rb][2][di]);
                        float ov = fmaf(0.5f, tanhapx(D[rb][3][di]), 0.5f);
                        const int ci = m * 4 + row * 2 + b;
                        float cn = fmaf(fv, cst[rb][ci], iv * gv);
                        cst[rb][ci] = cn;
                        hn[b] = ov * tanhapx(cn);
                        oacc[rb][row] = fmaf(hn[b], wo[m * 2 + b], oacc[rb][row]);
                    }
                    u32 ub0 = __float_as_uint(hn[0]);
                    u32 ub1 = __float_as_uint(hn[1]);
                    nAhi[rb][m >> 1][(m & 1) * 2 + row] = prmt_hi16(ub0, ub1);
                    float l0 = hn[0] - trunc_hi(hn[0]);
                    float l1 = hn[1] - trunc_hi(hn[1]);
                    nAlo[rb][m >> 1][(m & 1) * 2 + row] = cvt_bf16x2(l1, l0);
                }
        }

#pragma unroll
        for (int rb = 0; rb < 2; rb++)
#pragma unroll
            for (int kt = 0; kt < 2; kt++)
#pragma unroll
                for (int q = 0; q < 4; q++) {
                    Ahi[rb][kt][q] = nAhi[rb][kt][q];
                    Alo[rb][kt][q] = nAlo[rb][kt][q];
                }

        // ---- output projection: reduce over c (lanes xor 1,2) ----
#pragma unroll
        for (int rb = 0; rb < 2; rb++)
#pragma unroll
            for (int row = 0; row < 2; row++) {
                float o = oacc[rb][row];
                o += __shfl_xor_sync(0xffffffffu, o, 1);
                o += __shfl_xor_sync(0xffffffffu, o, 2);
                if (c == 0) out[brow[rb][row] * T_LEN + t] = o + bo;
            }
    }
}

extern "C" void kernel_launch(void* const* d_in, const int* in_sizes, int n_in,
                              void* d_out, int out_size) {
    const float* x     = (const float*)d_in[0];
    const float* W_ih  = (const float*)d_in[1];
    const float* W_hh  = (const float*)d_in[2];
    const float* b_ih  = (const float*)d_in[3];
    const float* b_hh  = (const float*)d_in[4];
    const float* W_out = (const float*)d_in[5];
    const float* b_out = (const float*)d_in[6];
    const float* h0    = (const float*)d_in[7];
    const float* c0    = (const float*)d_in[8];
    float* out = (float*)d_out;

    // 32768 batches / 64 per CTA (2 warps x 32) = 512 CTAs
    lsnn_kernel<<<512, 64>>>(x, W_ih, W_hh, b_ih, b_hh,
                             W_out, b_out, h0, c0, out);
}